// round 1
// baseline (speedup 1.0000x reference)
#include <cuda_runtime.h>

#define TT 128
#define BB 512
#define DD 512
#define OO 10

// Scratch (device-global: no allocations allowed in kernel_launch)
static __device__ float    g_Y[TT * BB * DD];        // cur1 pre-BN, [t][b][d]
static __device__ float    g_W1T[DD * DD];           // W1 transposed: [k][d]
static __device__ float    g_mean[TT * DD];
static __device__ float    g_rstd[TT * DD];
static __device__ unsigned g_spk[TT * BB * (DD / 32)]; // spk1 bit-packed along d
static __device__ float    g_cur2[TT * BB * OO];

// ---- packed fp32x2 helpers (FFMA2: full-rate fp32 on sm_103a) ----
__device__ __forceinline__ unsigned long long pk2(float lo, float hi) {
    unsigned long long r;
    asm("mov.b64 %0, {%1,%2};" : "=l"(r) : "f"(lo), "f"(hi));
    return r;
}
__device__ __forceinline__ void upk2(unsigned long long v, float& lo, float& hi) {
    asm("mov.b64 {%0,%1}, %2;" : "=f"(lo), "=f"(hi) : "l"(v));
}
__device__ __forceinline__ void ffma2(unsigned long long& c, unsigned long long a,
                                      unsigned long long b) {
    asm("fma.rn.f32x2 %0, %1, %2, %0;" : "+l"(c) : "l"(a), "l"(b));
}

// ---- W1 [d][k] -> g_W1T [k][d] so GEMM B-loads coalesce ----
__global__ void k_transpose(const float* __restrict__ W1) {
    __shared__ float tile[32][33];
    int x = blockIdx.x * 32 + threadIdx.x;
    int y0 = blockIdx.y * 32;
    #pragma unroll
    for (int j = threadIdx.y; j < 32; j += 8)
        tile[j][threadIdx.x] = W1[(y0 + j) * DD + x];
    __syncthreads();
    int x2 = blockIdx.y * 32 + threadIdx.x;
    int y2 = blockIdx.x * 32;
    #pragma unroll
    for (int j = threadIdx.y; j < 32; j += 8)
        g_W1T[(y2 + j) * DD + x2] = tile[threadIdx.x][j];
}

// ---- fused dropout + GEMM: Y[t*B+b][d] = sum_k mask[t,b,k]*data[b,t,k]*W1[d,k]
// 128x128x16 tiles, 8x8 per thread, packed f32x2 accumulators.
__global__ __launch_bounds__(256, 2) void k_gemm(const float* __restrict__ data,
                                                 const float* __restrict__ mask) {
    __shared__ float Xs[16][132];   // [k][row], padded
    __shared__ float Ws[16][128];   // [k][n]

    const int tid = threadIdx.x;
    const int bn = blockIdx.x;           // d-tile 0..3
    const int r0 = blockIdx.y * 128;     // row tile (rows share one t: 512%128==0)
    const int t = r0 >> 9;
    const int b0 = r0 & 511;
    const int n_base = bn * 128;

    const int xr = tid >> 2;             // 0..63 (plus +64)
    const int xk = (tid & 3) * 4;        // 0,4,8,12

    const float* dptr = data + ((long)b0 * TT + t) * DD;  // + row*T*D + k
    const float* mptr = mask + ((long)t * BB + b0) * DD;  // + row*D   + k

    unsigned long long cc[8][4];
    #pragma unroll
    for (int i = 0; i < 8; i++)
        #pragma unroll
        for (int j = 0; j < 4; j++) cc[i][j] = 0ULL;

    const int ty = tid >> 4, tx = tid & 15;
    const int m0 = ty * 8, n0 = tx * 8;

    for (int kt = 0; kt < DD; kt += 16) {
        __syncthreads();
        // X tile: apply dropout mask at load
        #pragma unroll
        for (int h = 0; h < 2; h++) {
            int row = xr + h * 64;
            float4 dv = *(const float4*)(dptr + (long)row * (TT * DD) + kt + xk);
            float4 mv = *(const float4*)(mptr + (long)row * DD + kt + xk);
            Xs[xk + 0][row] = dv.x * mv.x;
            Xs[xk + 1][row] = dv.y * mv.y;
            Xs[xk + 2][row] = dv.z * mv.z;
            Xs[xk + 3][row] = dv.w * mv.w;
        }
        // W tile (already transposed: contiguous in d)
        #pragma unroll
        for (int h = 0; h < 2; h++) {
            int idx = tid + h * 256;
            int k = idx >> 5;
            int n4 = (idx & 31) * 4;
            *(float4*)&Ws[k][n4] =
                *(const float4*)(g_W1T + (long)(kt + k) * DD + n_base + n4);
        }
        __syncthreads();
        #pragma unroll
        for (int k = 0; k < 16; k++) {
            float4 a0 = *(const float4*)&Xs[k][m0];
            float4 a1 = *(const float4*)&Xs[k][m0 + 4];
            ulonglong2 w01 = *(const ulonglong2*)&Ws[k][n0];
            ulonglong2 w23 = *(const ulonglong2*)&Ws[k][n0 + 4];
            float am[8] = {a0.x, a0.y, a0.z, a0.w, a1.x, a1.y, a1.z, a1.w};
            #pragma unroll
            for (int i = 0; i < 8; i++) {
                unsigned long long ap = pk2(am[i], am[i]);
                ffma2(cc[i][0], ap, w01.x);
                ffma2(cc[i][1], ap, w01.y);
                ffma2(cc[i][2], ap, w23.x);
                ffma2(cc[i][3], ap, w23.y);
            }
        }
    }
    float* yout = g_Y + (long)r0 * DD + n_base;
    #pragma unroll
    for (int i = 0; i < 8; i++) {
        float v[8];
        #pragma unroll
        for (int j = 0; j < 4; j++) upk2(cc[i][j], v[2 * j], v[2 * j + 1]);
        float4* p = (float4*)(yout + (long)(m0 + i) * DD + n0);
        p[0] = make_float4(v[0], v[1], v[2], v[3]);
        p[1] = make_float4(v[4], v[5], v[6], v[7]);
    }
}

// ---- BN stats per (t,d): two-pass mean/var over batch (matches reference) ----
__global__ void k_stats() {
    int idx = blockIdx.x * 256 + threadIdx.x;  // t*512 + d, 65536 total
    int t = idx >> 9, d = idx & 511;
    const float* col = g_Y + (long)t * BB * DD + d;
    float s = 0.f;
    for (int b = 0; b < BB; b++) s += col[(long)b * DD];
    float mean = s * (1.0f / BB);
    float v = 0.f;
    for (int b = 0; b < BB; b++) {
        float x = col[(long)b * DD] - mean;
        v += x * x;
    }
    float vpe = v * (1.0f / BB) + 1e-5f;
    g_mean[idx] = mean;
    g_rstd[idx] = (float)(1.0 / sqrt((double)vpe));  // match lax.rsqrt rounding
}

// ---- layer-1 membrane scan (pointwise over t), ballot-pack spikes ----
__global__ void k_scan1(const float* __restrict__ gamma,
                        const float* __restrict__ beta) {
    int id = blockIdx.x * 256 + threadIdx.x;  // b*512 + d
    int b = id >> 9, d = id & 511;
    int lane = threadIdx.x & 31;
    float g = gamma[d], be = beta[d];
    float mem = 0.f, spk = 0.f;
    const float* yp = g_Y + (long)b * DD + d;
    for (int t = 0; t < TT; t++) {
        float y = yp[(long)t * BB * DD];
        float cur = g * (y - g_mean[t * DD + d]) * g_rstd[t * DD + d] + be;
        mem = 0.5f * mem + cur - spk;           // BETA*mem + cur1 - spk1*THR
        spk = (mem - 1.0f) > 0.f ? 1.0f : 0.0f; // spike(mem - THR)
        unsigned bal = __ballot_sync(0xffffffffu, spk != 0.f);
        if (lane == 0) g_spk[((long)t * BB + b) * 16 + (d >> 5)] = bal;
    }
}

// ---- layer 2: cur2 = spk1 @ W2^T + b2, one warp per (t,b) row ----
__global__ __launch_bounds__(256) void k_layer2(const float* __restrict__ W2,
                                                const float* __restrict__ b2) {
    int r = blockIdx.x * 8 + (threadIdx.x >> 5);  // 0..65535
    int lane = threadIdx.x & 31;
    const unsigned* sp = g_spk + (long)r * 16;
    float acc[10];
    #pragma unroll
    for (int o = 0; o < 10; o++) acc[o] = 0.f;
    #pragma unroll
    for (int j = 0; j < 16; j++) {
        unsigned w = sp[j];
        float s = ((w >> lane) & 1u) ? 1.0f : 0.0f;
        int d = j * 32 + lane;
        #pragma unroll
        for (int o = 0; o < 10; o++) acc[o] += s * W2[o * DD + d];
    }
    #pragma unroll
    for (int o = 0; o < 10; o++) {
        #pragma unroll
        for (int off = 16; off; off >>= 1)
            acc[o] += __shfl_xor_sync(0xffffffffu, acc[o], off);
    }
    if (lane == 0) {
        float* out = g_cur2 + (long)r * 10;
        #pragma unroll
        for (int o = 0; o < 10; o++) out[o] = acc[o] + b2[o];
    }
}

// ---- layer-2 membrane scan + output ----
__global__ void k_scan2(float* __restrict__ out) {
    int id = blockIdx.x * 256 + threadIdx.x;  // b*10 + o, 5120 total
    if (id >= BB * OO) return;
    int b = id / 10, o = id - b * 10;
    float mem = 0.f, spk = 0.f;
    for (int t = 0; t < TT; t++) {
        float c = g_cur2[((long)t * BB + b) * 10 + o];
        mem = 0.5f * mem + c - spk;
        spk = (mem - 1.0f) > 0.f ? 1.0f : 0.0f;
        out[((long)t * BB + b) * 10 + o] = spk;
    }
}

extern "C" void kernel_launch(void* const* d_in, const int* in_sizes, int n_in,
                              void* d_out, int out_size) {
    const float* data  = (const float*)d_in[0];  // [B,T,D]
    const float* mask  = (const float*)d_in[1];  // [T,B,D]
    const float* W1    = (const float*)d_in[2];  // [D,D]
    // d_in[3] = b1: cancels exactly under BatchNorm (mean subtraction)
    const float* gamma = (const float*)d_in[4];
    const float* beta  = (const float*)d_in[5];
    const float* W2    = (const float*)d_in[6];  // [O,D]
    const float* b2    = (const float*)d_in[7];
    float* out = (float*)d_out;                  // [T,B,O]

    k_transpose<<<dim3(16, 16), dim3(32, 8)>>>(W1);
    k_gemm<<<dim3(4, 512), 256>>>(data, mask);
    k_stats<<<256, 256>>>();
    k_scan1<<<1024, 256>>>(gamma, beta);
    k_layer2<<<8192, 256>>>(W2, b2);
    k_scan2<<<20, 256>>>(out);
}